// round 13
// baseline (speedup 1.0000x reference)
#include <cuda_runtime.h>
#include <math.h>
#include <stdint.h>

#define Bv   32
#define QL   32
#define DOCL 2048
#define Sv   64
#define Ev   300
#define Hv   256
#define G3   768    // 3*H
#define KP   304    // padded K for GEMM
#define CLS  8      // cluster size

// ---------------- scratch ----------------
__device__ float g_facts[Bv*Sv*Ev];
__device__ float g_xg_q[Bv*QL*G3];
__device__ float g_xg_f[Bv*Sv*G3];
__device__ float g_xg_b[Bv*Sv*G3];

// packed 2xfp32 ops
#define FFMA2(acc, a, b) asm("fma.rn.f32x2 %0, %1, %2, %0;" : "+l"(acc) : "l"(a), "l"(b))
#define ADDF2(o, a, b)   asm("add.rn.f32x2 %0, %1, %2;" : "=l"(o) : "l"(a), "l"(b))
#define DUP2(d, s)       asm("mov.b64 %0, {%1, %1};" : "=l"(d) : "f"(s))

__device__ __forceinline__ void unpack2(unsigned long long v, float& lo, float& hi) {
    asm("mov.b64 {%0,%1}, %2;" : "=f"(lo), "=f"(hi) : "l"(v));
}
__device__ __forceinline__ float fast_sigmoid(float x) {
    return 1.f / (1.f + __expf(-x));
}
__device__ __forceinline__ float fast_tanh(float x) {
    return 2.f / (1.f + __expf(-2.f * x)) - 1.f;
}
__device__ __forceinline__ void mbar_wait_cluster(uint32_t mbar, uint32_t parity) {
    asm volatile(
        "{\n\t"
        ".reg .pred P;\n\t"
        "MWL_%=:\n\t"
        "mbarrier.try_wait.parity.acquire.cluster.shared::cta.b64 P, [%0], %1, 0x989680;\n\t"
        "@!P bra MWL_%=;\n\t"
        "}" :: "r"(mbar), "r"(parity) : "memory");
}

// ---------------- facts: ragged mean pooling + f_out zero + num_facts ----------------
__global__ void facts_kernel(const int* __restrict__ docs,
                             const int* __restrict__ slen,
                             const float* __restrict__ emb,
                             float* __restrict__ d_out) {
    __shared__ int toks[DOCL];
    int bs = blockIdx.x;
    int b = bs >> 6, s = bs & 63;

    // zero this block's 256-float slice of f_out (for GRU atomicAdd)
    if (threadIdx.x < 64) {
        reinterpret_cast<float4*>(d_out + Bv * Hv)[bs * 64 + threadIdx.x] =
            make_float4(0.f, 0.f, 0.f, 0.f);
    }
    // num_facts for batch b (one block per batch does it)
    if (s == 0 && threadIdx.x == 300) {
        int c = 0;
        const int* sl = slen + b * Sv;
        for (int ss = 0; ss < Sv; ss++) c += (sl[ss] > 0) ? 1 : 0;
        d_out[Bv * Hv + Bv * Sv * Hv + b] = (float)c;
    }

    const int* sl = slen + b * Sv;
    int start = 0;
    for (int i = 0; i < s; i++) start += sl[i];
    int len = sl[s];
    if (len > DOCL - start) len = DOCL - start;
    const int* dp = docs + b * DOCL + start;
    for (int i = threadIdx.x; i < len; i += blockDim.x) toks[i] = dp[i];
    __syncthreads();
    int e = threadIdx.x;
    if (e < Ev) {
        float a0 = 0.f, a1 = 0.f, a2 = 0.f, a3 = 0.f;
        float a4 = 0.f, a5 = 0.f, a6 = 0.f, a7 = 0.f;
        int i = 0;
        for (; i + 8 <= len; i += 8) {
            a0 += emb[(size_t)toks[i]     * Ev + e];
            a1 += emb[(size_t)toks[i + 1] * Ev + e];
            a2 += emb[(size_t)toks[i + 2] * Ev + e];
            a3 += emb[(size_t)toks[i + 3] * Ev + e];
            a4 += emb[(size_t)toks[i + 4] * Ev + e];
            a5 += emb[(size_t)toks[i + 5] * Ev + e];
            a6 += emb[(size_t)toks[i + 6] * Ev + e];
            a7 += emb[(size_t)toks[i + 7] * Ev + e];
        }
        for (; i < len; i++) a0 += emb[(size_t)toks[i] * Ev + e];
        float acc = ((a0 + a1) + (a2 + a3)) + ((a4 + a5) + (a6 + a7));
        float d = (len > 0) ? (float)len : 1.0f;
        g_facts[(size_t)bs * Ev + e] = acc / d;
    }
}

// ---------------- merged xg GEMM: 5120 x 768 x 304 (unchanged) ----------------
__global__ __launch_bounds__(512, 1) void xg_gemm(
        const int* __restrict__ queries, const float* __restrict__ emb,
        const float* __restrict__ qwih, const float* __restrict__ fwih,
        const float* __restrict__ bwih,
        const float* __restrict__ qbih, const float* __restrict__ fbih,
        const float* __restrict__ bbih) {
    __shared__ float As[16][264];
    __shared__ float Bs[16][132];

    int m0 = blockIdx.y * 256, n0 = blockIdx.x * 128;
    int which = (m0 < 1024) ? 0 : ((m0 < 3072) ? 1 : 2);
    int mbase = (which == 0) ? 0 : (which == 1) ? 1024 : 3072;
    const float* wih = (which == 0) ? qwih : (which == 1) ? fwih : bwih;
    const float* bih = (which == 0) ? qbih : (which == 1) ? fbih : bbih;
    float* outb = ((which == 0) ? g_xg_q : (which == 1) ? g_xg_f : g_xg_b)
                  + (size_t)(m0 - mbase) * G3;

    int tid = threadIdx.x, tx = tid & 15, ty = tid >> 4;

    const float* asrc[2];
    int ac[2];
#pragma unroll
    for (int i = 0; i < 2; i++) {
        int idx = tid + i * 512;
        int r = idx >> 2;
        ac[i] = idx & 3;
        int m = m0 + r;
        asrc[i] = (which == 0) ? (emb + (size_t)queries[m] * Ev)
                               : (g_facts + (size_t)(m - mbase) * Ev);
    }
    int ar0 = (tid) >> 2, ar1 = (tid + 512) >> 2;
    int bn = tid >> 2, bkq = tid & 3;
    const float* brow = wih + (size_t)(n0 + bn) * Ev;

    unsigned long long acc[8][4];
#pragma unroll
    for (int i = 0; i < 8; i++)
#pragma unroll
        for (int j = 0; j < 4; j++) acc[i][j] = 0ull;

    for (int k0 = 0; k0 < KP; k0 += 16) {
#pragma unroll
        for (int i = 0; i < 2; i++) {
            int k = k0 + ac[i] * 4;
            float4 av = (k < Ev) ? *reinterpret_cast<const float4*>(asrc[i] + k)
                                 : make_float4(0.f, 0.f, 0.f, 0.f);
            int r = (i == 0) ? ar0 : ar1;
            As[ac[i]*4+0][r] = av.x; As[ac[i]*4+1][r] = av.y;
            As[ac[i]*4+2][r] = av.z; As[ac[i]*4+3][r] = av.w;
        }
        {
            int k = k0 + bkq * 4;
            float4 bv = (k < Ev) ? *reinterpret_cast<const float4*>(brow + k)
                                 : make_float4(0.f, 0.f, 0.f, 0.f);
            Bs[bkq*4+0][bn] = bv.x; Bs[bkq*4+1][bn] = bv.y;
            Bs[bkq*4+2][bn] = bv.z; Bs[bkq*4+3][bn] = bv.w;
        }
        __syncthreads();
#pragma unroll
        for (int k = 0; k < 16; k++) {
            float4 a0 = *reinterpret_cast<const float4*>(&As[k][ty * 8]);
            float4 a1 = *reinterpret_cast<const float4*>(&As[k][ty * 8 + 4]);
            ulonglong2 b01 = *reinterpret_cast<const ulonglong2*>(&Bs[k][tx * 8]);
            ulonglong2 b23 = *reinterpret_cast<const ulonglong2*>(&Bs[k][tx * 8 + 4]);
            float af[8] = {a0.x, a0.y, a0.z, a0.w, a1.x, a1.y, a1.z, a1.w};
#pragma unroll
            for (int i = 0; i < 8; i++) {
                unsigned long long ad; DUP2(ad, af[i]);
                FFMA2(acc[i][0], ad, b01.x);
                FFMA2(acc[i][1], ad, b01.y);
                FFMA2(acc[i][2], ad, b23.x);
                FFMA2(acc[i][3], ad, b23.y);
            }
        }
        __syncthreads();
    }
#pragma unroll
    for (int i = 0; i < 8; i++) {
        float* orow = outb + (size_t)(ty * 8 + i) * G3 + n0 + tx * 8;
#pragma unroll
        for (int jp = 0; jp < 4; jp++) {
            float lo, hi; unpack2(acc[i][jp], lo, hi);
            orow[2*jp]   = lo + bih[n0 + tx*8 + 2*jp];
            orow[2*jp+1] = hi + bih[n0 + tx*8 + 2*jp + 1];
        }
    }
}

// ---------------- GRU: producer/consumer barriers, shfl-split reduce ----------------
// 12 clusters x 8 CTAs x 512 threads.
// Dot role:  ud = tid&31, kq = tid>>5 (16 k each); warp kq waits only rank kq>>1's slice.
// After posting partials, warps 8-15 bar.arrive (parity-alternating id 2/3) and run
// ahead into the next step's dot; gate warps 0-7 bar.sync, then reduce+gates+broadcast.
#define RED_USTR 205
#define RED_GSTR 17
#define REDBUF  (32 * RED_USTR)   // u64 per parity buffer
extern "C" __global__ void __cluster_dims__(CLS, 1, 1) __launch_bounds__(512, 1)
gru_cluster(const int* __restrict__ qlen,
            const float* __restrict__ qwhh, const float* __restrict__ fwhh,
            const float* __restrict__ bwhh,
            const float* __restrict__ qbhh, const float* __restrict__ fbhh,
            const float* __restrict__ bbhh,
            float* __restrict__ d_out) {
    extern __shared__ float sm[];
    float* swp = sm;                                         // 24576 floats
    float* shT = sm + 24576;                                 // 4096 floats [2][256][8]
    unsigned long long* redv = (unsigned long long*)(sm + 24576 + 4096);  // 2 x REDBUF
    float* stg = (float*)(redv + 2 * REDBUF);                // [4][256]
    unsigned long long* mbar = (unsigned long long*)(stg + 1024);  // [8]

    int cid = blockIdx.x / CLS;
    int crank = blockIdx.x - cid * CLS;
    int gru = cid >> 2, bg = cid & 3;
    int tid = threadIdx.x;

    const float* whh = (gru == 0) ? qwhh : (gru == 1) ? fwhh : bwhh;
    const float* bhh = (gru == 0) ? qbhh : (gru == 1) ? fbhh : bbhh;
    const float* xg  = (gru == 0) ? g_xg_q : (gru == 1) ? g_xg_f : g_xg_b;
    float* fout = d_out + Bv * Hv;
    int T = (gru == 0) ? QL : Sv;

    uint32_t shT_u32, mbar_u32, stg_u32;
    asm("{ .reg .u64 t; cvta.to.shared.u64 t, %1; cvt.u32.u64 %0, t; }"
        : "=r"(shT_u32) : "l"(shT));
    asm("{ .reg .u64 t; cvta.to.shared.u64 t, %1; cvt.u32.u64 %0, t; }"
        : "=r"(mbar_u32) : "l"(mbar));
    asm("{ .reg .u64 t; cvta.to.shared.u64 t, %1; cvt.u32.u64 %0, t; }"
        : "=r"(stg_u32) : "l"(stg));

    // ---- init: repack weights; zero h + stg; init 8 mbarriers; arm phase 0 ----
    for (int i = tid; i < 96 * 64; i += 512) {
        int gi = i >> 6, k4 = i & 63;
        int g = gi >> 5, u = gi & 31;
        float4 v = *reinterpret_cast<const float4*>(
            &whh[(size_t)((g << 8) + (crank << 5) + u) * Hv + (k4 << 2)]);
        int kq = k4 >> 2, j4 = k4 & 3;
        *reinterpret_cast<float4*>(&swp[(((kq * 3 + g) << 2) + j4) * 128 + (u << 2)]) = v;
    }
    for (int i = tid; i < 4096; i += 512) shT[i] = 0.f;
    for (int i = tid; i < 1024; i += 512) stg[i] = 0.f;
    if (tid < 8) {
        asm volatile("mbarrier.init.shared.b64 [%0], %1;"
                     :: "r"(mbar_u32 + tid * 8), "r"(1) : "memory");
        asm volatile("mbarrier.arrive.expect_tx.shared.b64 _, [%0], %1;"
                     :: "r"(mbar_u32 + tid * 8), "r"(1024) : "memory");
    }
    __syncthreads();
    asm volatile("barrier.cluster.arrive.aligned;" ::: "memory");
    asm volatile("barrier.cluster.wait.aligned;"   ::: "memory");

    // ---- dot role: r and z gate weights in registers ----
    int ud = tid & 31, kq = tid >> 5;
    float wrreg[16], wzreg[16];
#pragma unroll
    for (int j4 = 0; j4 < 4; j4++) {
        float4 wv = *reinterpret_cast<const float4*>(
            &swp[(((kq * 3 + 0) << 2) + j4) * 128 + (ud << 2)]);
        wrreg[(j4 << 2) + 0] = wv.x; wrreg[(j4 << 2) + 1] = wv.y;
        wrreg[(j4 << 2) + 2] = wv.z; wrreg[(j4 << 2) + 3] = wv.w;
        float4 zv = *reinterpret_cast<const float4*>(
            &swp[(((kq * 3 + 1) << 2) + j4) * 128 + (ud << 2)]);
        wzreg[(j4 << 2) + 0] = zv.x; wzreg[(j4 << 2) + 1] = zv.y;
        wzreg[(j4 << 2) + 2] = zv.z; wzreg[(j4 << 2) + 3] = zv.w;
    }
    uint32_t mywait = mbar_u32 + (uint32_t)((kq >> 1) << 3);
    bool armer = ((tid & 63) == 0);

    // ---- gate role: tid<256, 1 batch each ----
    int ug = tid >> 3, bl = tid & 7;
    int ugx = (crank << 5) + ug;
    int bgl = (bg << 3) + bl;
    float br = 0.f, bz = 0.f, bn2 = 0.f;
    int qm1 = -2;
    const float* xgb = nullptr;
    if (tid < 256) {
        br = bhh[ugx]; bz = bhh[256 + ugx]; bn2 = bhh[512 + ugx];
        if (gru == 0) qm1 = qlen[bgl] - 1;
        xgb = xg + (size_t)bgl * T * G3;
    }
    int half8 = (bl & 1) ? 8 : 0;   // reduce half for lane-pair split

    // bulk-copy role (tid<8)
    uint32_t dstA = 0, dstB = 0, rmbar = 0;
    if (tid < 8) {
        uint32_t l0 = shT_u32 + 8192u + (uint32_t)(crank << 10);  // p=0 -> buf1
        uint32_t l1 = shT_u32 + (uint32_t)(crank << 10);          // p=1 -> buf0
        uint32_t lm = mbar_u32 + (uint32_t)(crank << 3);
        asm("mapa.shared::cluster.u32 %0, %1, %2;" : "=r"(dstA)  : "r"(l0), "r"(tid));
        asm("mapa.shared::cluster.u32 %0, %1, %2;" : "=r"(dstB)  : "r"(l1), "r"(tid));
        asm("mapa.shared::cluster.u32 %0, %1, %2;" : "=r"(rmbar) : "r"(lm), "r"(tid));
    }

    int redbase_st = ud * RED_USTR + kq;

    for (int step = 0; step < T; step++) {
        int t = (gru == 2) ? (T - 1 - step) : step;
        int p = step & 1;
        int ps = step & 3;
        int pprev = (step - 1) & 3;
        unsigned long long* redq = redv + (size_t)(step & 1) * REDBUF;

        // gate-role x prefetch (independent of h slices)
        float ir = 0.f, iz = 0.f, in_ = 0.f, hold = 0.f;
        if (tid < 256) {
            const float* xr = xgb + (size_t)t * G3;
            ir = xr[ugx]; iz = xr[256 + ugx]; in_ = xr[512 + ugx];
            hold = stg[(pprev << 8) + (ug << 3) + bl];
        }

        // per-warp wait for the one needed slice, then re-arm that barrier
        if (step > 0) {
            mbar_wait_cluster(mywait, (uint32_t)((step - 1) & 1));
            if (armer) {
                asm volatile("mbarrier.arrive.expect_tx.shared.b64 _, [%0], %1;"
                             :: "r"(mywait), "r"(1024) : "memory");
            }
        }

        // ---- dot: 3 gates x 16 k x 8 batches per thread ----
        unsigned long long acc[3][4];
#pragma unroll
        for (int g = 0; g < 3; g++)
#pragma unroll
            for (int b = 0; b < 4; b++) acc[g][b] = 0ull;

        const float* hT = shT + ((p << 8) + (kq << 4)) * 8;
#pragma unroll
        for (int j4 = 0; j4 < 4; j4++) {
            ulonglong2 h01[4], h45[4];
#pragma unroll
            for (int kk = 0; kk < 4; kk++) {
                const ulonglong2* hr = reinterpret_cast<const ulonglong2*>(
                    hT + ((j4 << 2) + kk) * 8);
                h01[kk] = hr[0];
                h45[kk] = hr[1];
            }
#pragma unroll
            for (int kk = 0; kk < 4; kk++) {
                unsigned long long wd; DUP2(wd, wrreg[(j4 << 2) + kk]);
                FFMA2(acc[0][0], wd, h01[kk].x);
                FFMA2(acc[0][1], wd, h01[kk].y);
                FFMA2(acc[0][2], wd, h45[kk].x);
                FFMA2(acc[0][3], wd, h45[kk].y);
            }
#pragma unroll
            for (int kk = 0; kk < 4; kk++) {
                unsigned long long wd; DUP2(wd, wzreg[(j4 << 2) + kk]);
                FFMA2(acc[1][0], wd, h01[kk].x);
                FFMA2(acc[1][1], wd, h01[kk].y);
                FFMA2(acc[1][2], wd, h45[kk].x);
                FFMA2(acc[1][3], wd, h45[kk].y);
            }
            {
                float4 wv = *reinterpret_cast<const float4*>(
                    &swp[(((kq * 3 + 2) << 2) + j4) * 128 + (ud << 2)]);
                float wf[4] = {wv.x, wv.y, wv.z, wv.w};
#pragma unroll
                for (int kk = 0; kk < 4; kk++) {
                    unsigned long long wd; DUP2(wd, wf[kk]);
                    FFMA2(acc[2][0], wd, h01[kk].x);
                    FFMA2(acc[2][1], wd, h01[kk].y);
                    FFMA2(acc[2][2], wd, h45[kk].x);
                    FFMA2(acc[2][3], wd, h45[kk].y);
                }
            }
        }
#pragma unroll
        for (int g = 0; g < 3; g++)
#pragma unroll
            for (int b = 0; b < 4; b++)
                redq[redbase_st + ((g << 2) + b) * RED_GSTR] = acc[g][b];

        // producer/consumer split: warps 8-15 arrive and run ahead;
        // gate warps 0-7 sync, then reduce+gates+broadcast.
        if (tid < 256) {
            if (p) { asm volatile("bar.sync 3, 512;" ::: "memory"); }
            else   { asm volatile("bar.sync 2, 512;" ::: "memory"); }

            // ---- lane-pair split reduce: each lane sums its 8-kq half, shfl merge ----
            unsigned long long s[3];
#pragma unroll
            for (int g = 0; g < 3; g++) {
                const unsigned long long* rp =
                    redq + ug * RED_USTR + ((g << 2) + (bl >> 1)) * RED_GSTR + half8;
                unsigned long long a0 = rp[0], a1 = rp[1], a2 = rp[2], a3 = rp[3];
                ADDF2(a0, a0, rp[4]); ADDF2(a1, a1, rp[5]);
                ADDF2(a2, a2, rp[6]); ADDF2(a3, a3, rp[7]);
                ADDF2(a0, a0, a1); ADDF2(a2, a2, a3);
                ADDF2(a0, a0, a2);
                unsigned long long other =
                    __shfl_xor_sync(0xFFFFFFFFu, a0, 1);
                ADDF2(a0, a0, other);
                s[g] = a0;
            }
            float lo, hi;
            unpack2(s[0], lo, hi); float ghr = (bl & 1) ? hi : lo;
            unpack2(s[1], lo, hi); float ghz = (bl & 1) ? hi : lo;
            unpack2(s[2], lo, hi); float ghn = (bl & 1) ? hi : lo;

            float r = fast_sigmoid(ir + ghr + br);
            float z = fast_sigmoid(iz + ghz + bz);
            float n = fast_tanh(in_ + r * (ghn + bn2));
            float hnew = (1.f - z) * n + z * hold;

            stg[(ps << 8) + (ug << 3) + bl] = hnew;
            asm volatile("bar.sync 1, 256;" ::: "memory");

            // broadcast: 8 async 1KB bulk copies crediting peers' mbar[crank]
            if (tid < 8) {
                asm volatile("fence.proxy.async.shared::cta;" ::: "memory");
                uint32_t dst = p ? dstB : dstA;
                uint32_t src = stg_u32 + (uint32_t)(ps << 10);
                asm volatile(
                    "cp.async.bulk.shared::cluster.shared::cta.mbarrier::complete_tx::bytes "
                    "[%0], [%1], %2, [%3];"
                    :: "r"(dst), "r"(src), "r"(1024), "r"(rmbar) : "memory");
            }
            // gmem output overlaps the in-flight broadcast
            if (gru == 0) {
                if (t == qm1) d_out[(size_t)bgl * Hv + ugx] = hnew;
            } else {
                atomicAdd(&fout[((size_t)bgl * Sv + t) * Hv + ugx], hnew);
            }
        } else {
            if (p) { asm volatile("bar.arrive 3, 512;" ::: "memory"); }
            else   { asm volatile("bar.arrive 2, 512;" ::: "memory"); }
            // run ahead into next step's slice wait + dot
        }
    }

    // ---- drain ----
    if (tid < 8) {
        asm volatile("cp.async.bulk.commit_group;" ::: "memory");
        asm volatile("cp.async.bulk.wait_group 0;" ::: "memory");
        mbar_wait_cluster(mbar_u32 + tid * 8, (uint32_t)((T - 1) & 1));
    }
    __syncthreads();
    asm volatile("barrier.cluster.arrive.aligned;" ::: "memory");
    asm volatile("barrier.cluster.wait.aligned;"   ::: "memory");
}

// ---------------- launch ----------------
extern "C" void kernel_launch(void* const* d_in, const int* in_sizes, int n_in,
                              void* d_out, int out_size) {
    const int*   queries = (const int*)d_in[0];
    const int*   qlen    = (const int*)d_in[1];
    const int*   docs    = (const int*)d_in[2];
    const int*   slen    = (const int*)d_in[3];
    const float* emb     = (const float*)d_in[4];
    const float* q_wih   = (const float*)d_in[5];
    const float* q_whh   = (const float*)d_in[6];
    const float* q_bih   = (const float*)d_in[7];
    const float* q_bhh   = (const float*)d_in[8];
    const float* f_wih   = (const float*)d_in[9];
    const float* f_whh   = (const float*)d_in[10];
    const float* f_bih   = (const float*)d_in[11];
    const float* f_bhh   = (const float*)d_in[12];
    const float* b_wih   = (const float*)d_in[13];
    const float* b_whh   = (const float*)d_in[14];
    const float* b_bih   = (const float*)d_in[15];
    const float* b_bhh   = (const float*)d_in[16];
    float* out = (float*)d_out;

    // bytes: swp 98304 + shT 16384 + redv 104960 + stg 4096 + mbars/pad 96
    const int GRU_SMEM = 24576 * 4 + 4096 * 4 + 2 * REDBUF * 8 + 1024 * 4 + 96;
    cudaFuncSetAttribute(gru_cluster, cudaFuncAttributeMaxDynamicSharedMemorySize, GRU_SMEM);

    facts_kernel<<<Bv * Sv, 320>>>(docs, slen, emb, out);

    dim3 gg(6, 20);
    xg_gemm<<<gg, 512>>>(queries, emb, q_wih, f_wih, b_wih, q_bih, f_bih, b_bih);

    gru_cluster<<<96, 512, GRU_SMEM>>>(qlen, q_whh, f_whh, b_whh,
                                       q_bhh, f_bhh, b_bhh, out);
}

// round 14
// speedup vs baseline: 1.0382x; 1.0382x over previous
#include <cuda_runtime.h>
#include <math.h>
#include <stdint.h>

#define Bv   32
#define QL   32
#define DOCL 2048
#define Sv   64
#define Ev   300
#define Hv   256
#define G3   768    // 3*H
#define KP   304    // padded K for GEMM
#define CLS  8      // cluster size

// ---------------- scratch ----------------
__device__ float g_facts[Bv*Sv*Ev];
__device__ float g_xg_q[Bv*QL*G3];
__device__ float g_xg_f[Bv*Sv*G3];
__device__ float g_xg_b[Bv*Sv*G3];

// packed 2xfp32 ops
#define FFMA2(acc, a, b) asm("fma.rn.f32x2 %0, %1, %2, %0;" : "+l"(acc) : "l"(a), "l"(b))
#define ADDF2(o, a, b)   asm("add.rn.f32x2 %0, %1, %2;" : "=l"(o) : "l"(a), "l"(b))
#define DUP2(d, s)       asm("mov.b64 %0, {%1, %1};" : "=l"(d) : "f"(s))

__device__ __forceinline__ void unpack2(unsigned long long v, float& lo, float& hi) {
    asm("mov.b64 {%0,%1}, %2;" : "=f"(lo), "=f"(hi) : "l"(v));
}
__device__ __forceinline__ float fast_sigmoid(float x) {
    return 1.f / (1.f + __expf(-x));
}
__device__ __forceinline__ float fast_tanh(float x) {
    return 2.f / (1.f + __expf(-2.f * x)) - 1.f;
}
__device__ __forceinline__ void mbar_wait_cluster(uint32_t mbar, uint32_t parity) {
    asm volatile(
        "{\n\t"
        ".reg .pred P;\n\t"
        "MWL_%=:\n\t"
        "mbarrier.try_wait.parity.acquire.cluster.shared::cta.b64 P, [%0], %1, 0x989680;\n\t"
        "@!P bra MWL_%=;\n\t"
        "}" :: "r"(mbar), "r"(parity) : "memory");
}

// ---------------- facts: ragged mean pooling + f_out zero + num_facts ----------------
__global__ void facts_kernel(const int* __restrict__ docs,
                             const int* __restrict__ slen,
                             const float* __restrict__ emb,
                             float* __restrict__ d_out) {
    __shared__ int toks[DOCL];
    int bs = blockIdx.x;
    int b = bs >> 6, s = bs & 63;

    // zero this block's 256-float slice of f_out (for GRU atomicAdd)
    if (threadIdx.x < 64) {
        reinterpret_cast<float4*>(d_out + Bv * Hv)[bs * 64 + threadIdx.x] =
            make_float4(0.f, 0.f, 0.f, 0.f);
    }
    // num_facts for batch b (one block per batch does it)
    if (s == 0 && threadIdx.x == 300) {
        int c = 0;
        const int* sl = slen + b * Sv;
        for (int ss = 0; ss < Sv; ss++) c += (sl[ss] > 0) ? 1 : 0;
        d_out[Bv * Hv + Bv * Sv * Hv + b] = (float)c;
    }

    const int* sl = slen + b * Sv;
    int start = 0;
    for (int i = 0; i < s; i++) start += sl[i];
    int len = sl[s];
    if (len > DOCL - start) len = DOCL - start;
    const int* dp = docs + b * DOCL + start;
    for (int i = threadIdx.x; i < len; i += blockDim.x) toks[i] = dp[i];
    __syncthreads();
    int e = threadIdx.x;
    if (e < Ev) {
        float a0 = 0.f, a1 = 0.f, a2 = 0.f, a3 = 0.f;
        int i = 0;
        for (; i + 4 <= len; i += 4) {
            a0 += emb[(size_t)toks[i]     * Ev + e];
            a1 += emb[(size_t)toks[i + 1] * Ev + e];
            a2 += emb[(size_t)toks[i + 2] * Ev + e];
            a3 += emb[(size_t)toks[i + 3] * Ev + e];
        }
        for (; i < len; i++) a0 += emb[(size_t)toks[i] * Ev + e];
        float acc = (a0 + a1) + (a2 + a3);
        float d = (len > 0) ? (float)len : 1.0f;
        g_facts[(size_t)bs * Ev + e] = acc / d;
    }
}

// ---------------- merged xg GEMM: 5120 x 768 x 304 ----------------
// Single-sync ping-pong smem + register prefetch: LDGs for tile k+1 overlap
// the compute of tile k; one __syncthreads per tile.
__global__ __launch_bounds__(512, 1) void xg_gemm(
        const int* __restrict__ queries, const float* __restrict__ emb,
        const float* __restrict__ qwih, const float* __restrict__ fwih,
        const float* __restrict__ bwih,
        const float* __restrict__ qbih, const float* __restrict__ fbih,
        const float* __restrict__ bbih) {
    __shared__ float As[2][16][264];
    __shared__ float Bs[2][16][132];

    int m0 = blockIdx.y * 256, n0 = blockIdx.x * 128;
    int which = (m0 < 1024) ? 0 : ((m0 < 3072) ? 1 : 2);
    int mbase = (which == 0) ? 0 : (which == 1) ? 1024 : 3072;
    const float* wih = (which == 0) ? qwih : (which == 1) ? fwih : bwih;
    const float* bih = (which == 0) ? qbih : (which == 1) ? fbih : bbih;
    float* outb = ((which == 0) ? g_xg_q : (which == 1) ? g_xg_f : g_xg_b)
                  + (size_t)(m0 - mbase) * G3;

    int tid = threadIdx.x, tx = tid & 15, ty = tid >> 4;

    const float* asrc[2];
    int ac[2];
#pragma unroll
    for (int i = 0; i < 2; i++) {
        int idx = tid + i * 512;
        int r = idx >> 2;
        ac[i] = idx & 3;
        int m = m0 + r;
        asrc[i] = (which == 0) ? (emb + (size_t)queries[m] * Ev)
                               : (g_facts + (size_t)(m - mbase) * Ev);
    }
    int ar0 = (tid) >> 2, ar1 = (tid + 512) >> 2;
    int bn = tid >> 2, bkq = tid & 3;
    const float* brow = wih + (size_t)(n0 + bn) * Ev;

    unsigned long long acc[8][4];
#pragma unroll
    for (int i = 0; i < 8; i++)
#pragma unroll
        for (int j = 0; j < 4; j++) acc[i][j] = 0ull;

    float4 avp0, avp1, bvp;
#define LOAD_REGS(K0) do {                                                    \
        int k0_ = (K0);                                                       \
        int ka0 = k0_ + ac[0] * 4, ka1 = k0_ + ac[1] * 4, kb = k0_ + bkq * 4; \
        avp0 = (ka0 < Ev) ? *reinterpret_cast<const float4*>(asrc[0] + ka0)   \
                          : make_float4(0.f, 0.f, 0.f, 0.f);                  \
        avp1 = (ka1 < Ev) ? *reinterpret_cast<const float4*>(asrc[1] + ka1)   \
                          : make_float4(0.f, 0.f, 0.f, 0.f);                  \
        bvp  = (kb  < Ev) ? *reinterpret_cast<const float4*>(brow + kb)       \
                          : make_float4(0.f, 0.f, 0.f, 0.f);                  \
    } while (0)

    LOAD_REGS(0);

    for (int kt = 0; kt < KP / 16; kt++) {
        int buf = kt & 1;
        // store prefetched tile
        As[buf][ac[0]*4+0][ar0] = avp0.x; As[buf][ac[0]*4+1][ar0] = avp0.y;
        As[buf][ac[0]*4+2][ar0] = avp0.z; As[buf][ac[0]*4+3][ar0] = avp0.w;
        As[buf][ac[1]*4+0][ar1] = avp1.x; As[buf][ac[1]*4+1][ar1] = avp1.y;
        As[buf][ac[1]*4+2][ar1] = avp1.z; As[buf][ac[1]*4+3][ar1] = avp1.w;
        Bs[buf][bkq*4+0][bn] = bvp.x; Bs[buf][bkq*4+1][bn] = bvp.y;
        Bs[buf][bkq*4+2][bn] = bvp.z; Bs[buf][bkq*4+3][bn] = bvp.w;
        __syncthreads();

        // prefetch next tile (overlaps compute below)
        if (kt + 1 < KP / 16) LOAD_REGS((kt + 1) * 16);

#pragma unroll
        for (int k = 0; k < 16; k++) {
            float4 a0 = *reinterpret_cast<const float4*>(&As[buf][k][ty * 8]);
            float4 a1 = *reinterpret_cast<const float4*>(&As[buf][k][ty * 8 + 4]);
            ulonglong2 b01 = *reinterpret_cast<const ulonglong2*>(&Bs[buf][k][tx * 8]);
            ulonglong2 b23 = *reinterpret_cast<const ulonglong2*>(&Bs[buf][k][tx * 8 + 4]);
            float af[8] = {a0.x, a0.y, a0.z, a0.w, a1.x, a1.y, a1.z, a1.w};
#pragma unroll
            for (int i = 0; i < 8; i++) {
                unsigned long long ad; DUP2(ad, af[i]);
                FFMA2(acc[i][0], ad, b01.x);
                FFMA2(acc[i][1], ad, b01.y);
                FFMA2(acc[i][2], ad, b23.x);
                FFMA2(acc[i][3], ad, b23.y);
            }
        }
        // no second sync: next store targets the other buffer, which was last
        // read two iterations ago (ordered by the sync above)
    }
#undef LOAD_REGS
#pragma unroll
    for (int i = 0; i < 8; i++) {
        float* orow = outb + (size_t)(ty * 8 + i) * G3 + n0 + tx * 8;
#pragma unroll
        for (int jp = 0; jp < 4; jp++) {
            float lo, hi; unpack2(acc[i][jp], lo, hi);
            orow[2*jp]   = lo + bih[n0 + tx*8 + 2*jp];
            orow[2*jp+1] = hi + bih[n0 + tx*8 + 2*jp + 1];
        }
    }
}

// ---------------- GRU: per-slice mbarriers, wait-then-arm protocol (R11 exact) ----
// 12 clusters x 8 CTAs x 512 threads.
#define RED_USTR 205
#define RED_GSTR 17
#define REDBUF  (32 * RED_USTR)   // u64 per parity buffer
extern "C" __global__ void __cluster_dims__(CLS, 1, 1) __launch_bounds__(512, 1)
gru_cluster(const int* __restrict__ qlen,
            const float* __restrict__ qwhh, const float* __restrict__ fwhh,
            const float* __restrict__ bwhh,
            const float* __restrict__ qbhh, const float* __restrict__ fbhh,
            const float* __restrict__ bbhh,
            float* __restrict__ d_out) {
    extern __shared__ float sm[];
    float* swp = sm;                                         // 24576 floats
    float* shT = sm + 24576;                                 // 4096 floats [2][256][8]
    unsigned long long* redv = (unsigned long long*)(sm + 24576 + 4096);  // 2 x REDBUF
    float* stg = (float*)(redv + 2 * REDBUF);                // [4][256]
    unsigned long long* mbar = (unsigned long long*)(stg + 1024);  // [8]

    int cid = blockIdx.x / CLS;
    int crank = blockIdx.x - cid * CLS;
    int gru = cid >> 2, bg = cid & 3;
    int tid = threadIdx.x;

    const float* whh = (gru == 0) ? qwhh : (gru == 1) ? fwhh : bwhh;
    const float* bhh = (gru == 0) ? qbhh : (gru == 1) ? fbhh : bbhh;
    const float* xg  = (gru == 0) ? g_xg_q : (gru == 1) ? g_xg_f : g_xg_b;
    float* fout = d_out + Bv * Hv;
    int T = (gru == 0) ? QL : Sv;

    uint32_t shT_u32, mbar_u32, stg_u32;
    asm("{ .reg .u64 t; cvta.to.shared.u64 t, %1; cvt.u32.u64 %0, t; }"
        : "=r"(shT_u32) : "l"(shT));
    asm("{ .reg .u64 t; cvta.to.shared.u64 t, %1; cvt.u32.u64 %0, t; }"
        : "=r"(mbar_u32) : "l"(mbar));
    asm("{ .reg .u64 t; cvta.to.shared.u64 t, %1; cvt.u32.u64 %0, t; }"
        : "=r"(stg_u32) : "l"(stg));

    // ---- init: repack weights; zero h + stg; init 8 mbarriers; arm phase 0 ----
    for (int i = tid; i < 96 * 64; i += 512) {
        int gi = i >> 6, k4 = i & 63;
        int g = gi >> 5, u = gi & 31;
        float4 v = *reinterpret_cast<const float4*>(
            &whh[(size_t)((g << 8) + (crank << 5) + u) * Hv + (k4 << 2)]);
        int kq = k4 >> 2, j4 = k4 & 3;
        *reinterpret_cast<float4*>(&swp[(((kq * 3 + g) << 2) + j4) * 128 + (u << 2)]) = v;
    }
    for (int i = tid; i < 4096; i += 512) shT[i] = 0.f;
    for (int i = tid; i < 1024; i += 512) stg[i] = 0.f;
    if (tid < 8) {
        asm volatile("mbarrier.init.shared.b64 [%0], %1;"
                     :: "r"(mbar_u32 + tid * 8), "r"(1) : "memory");
        asm volatile("mbarrier.arrive.expect_tx.shared.b64 _, [%0], %1;"
                     :: "r"(mbar_u32 + tid * 8), "r"(1024) : "memory");
    }
    __syncthreads();
    asm volatile("barrier.cluster.arrive.aligned;" ::: "memory");
    asm volatile("barrier.cluster.wait.aligned;"   ::: "memory");

    // ---- dot role: r and z gate weights in registers ----
    int ud = tid & 31, kq = tid >> 5;
    float wrreg[16], wzreg[16];
#pragma unroll
    for (int j4 = 0; j4 < 4; j4++) {
        float4 wv = *reinterpret_cast<const float4*>(
            &swp[(((kq * 3 + 0) << 2) + j4) * 128 + (ud << 2)]);
        wrreg[(j4 << 2) + 0] = wv.x; wrreg[(j4 << 2) + 1] = wv.y;
        wrreg[(j4 << 2) + 2] = wv.z; wrreg[(j4 << 2) + 3] = wv.w;
        float4 zv = *reinterpret_cast<const float4*>(
            &swp[(((kq * 3 + 1) << 2) + j4) * 128 + (ud << 2)]);
        wzreg[(j4 << 2) + 0] = zv.x; wzreg[(j4 << 2) + 1] = zv.y;
        wzreg[(j4 << 2) + 2] = zv.z; wzreg[(j4 << 2) + 3] = zv.w;
    }
    uint32_t mywait = mbar_u32 + (uint32_t)((kq >> 1) << 3);
    bool armer = ((tid & 63) == 0);

    // ---- gate role: tid<256, 1 batch each ----
    int ug = tid >> 3, bl = tid & 7;
    int ugx = (crank << 5) + ug;
    int bgl = (bg << 3) + bl;
    float br = 0.f, bz = 0.f, bn2 = 0.f;
    int qm1 = -2;
    const float* xgb = nullptr;
    if (tid < 256) {
        br = bhh[ugx]; bz = bhh[256 + ugx]; bn2 = bhh[512 + ugx];
        if (gru == 0) qm1 = qlen[bgl] - 1;
        xgb = xg + (size_t)bgl * T * G3;
    }

    // bulk-copy role (tid<8)
    uint32_t dstA = 0, dstB = 0, rmbar = 0;
    if (tid < 8) {
        uint32_t l0 = shT_u32 + 8192u + (uint32_t)(crank << 10);  // p=0 -> buf1
        uint32_t l1 = shT_u32 + (uint32_t)(crank << 10);          // p=1 -> buf0
        uint32_t lm = mbar_u32 + (uint32_t)(crank << 3);
        asm("mapa.shared::cluster.u32 %0, %1, %2;" : "=r"(dstA)  : "r"(l0), "r"(tid));
        asm("mapa.shared::cluster.u32 %0, %1, %2;" : "=r"(dstB)  : "r"(l1), "r"(tid));
        asm("mapa.shared::cluster.u32 %0, %1, %2;" : "=r"(rmbar) : "r"(lm), "r"(tid));
    }

    int redbase_st = ud * RED_USTR + kq;

    for (int step = 0; step < T; step++) {
        int t = (gru == 2) ? (T - 1 - step) : step;
        int p = step & 1;
        int ps = step & 3;
        int pprev = (step - 1) & 3;
        unsigned long long* redq = redv + (size_t)(step & 1) * REDBUF;

        // gate-role x prefetch (independent of h slices)
        float ir = 0.f, iz = 0.f, in_ = 0.f, hold = 0.f;
        if (tid < 256) {
            const float* xr = xgb + (size_t)t * G3;
            ir = xr[ugx]; iz = xr[256 + ugx]; in_ = xr[512 + ugx];
            hold = stg[(pprev << 8) + (ug << 3) + bl];
        }

        // per-warp wait for the one needed slice, then re-arm that barrier
        if (step > 0) {
            mbar_wait_cluster(mywait, (uint32_t)((step - 1) & 1));
            if (armer) {
                asm volatile("mbarrier.arrive.expect_tx.shared.b64 _, [%0], %1;"
                             :: "r"(mywait), "r"(1024) : "memory");
            }
        }

        // ---- dot: 3 gates x 16 k x 8 batches per thread ----
        unsigned long long acc[3][4];
#pragma unroll
        for (int g = 0; g < 3; g++)
#pragma unroll
            for (int b = 0; b < 4; b++) acc[g][b] = 0ull;

        const float* hT = shT + ((p << 8) + (kq << 4)) * 8;
#pragma unroll
        for (int j4 = 0; j4 < 4; j4++) {
            ulonglong2 h01[4], h45[4];
#pragma unroll
            for (int kk = 0; kk < 4; kk++) {
                const ulonglong2* hr = reinterpret_cast<const ulonglong2*>(
                    hT + ((j4 << 2) + kk) * 8);
                h01[kk] = hr[0];
                h45[kk] = hr[1];
            }
#pragma unroll
            for (int kk = 0; kk < 4; kk++) {
                unsigned long long wd; DUP2(wd, wrreg[(j4 << 2) + kk]);
                FFMA2(acc[0][0], wd, h01[kk].x);
                FFMA2(acc[0][1], wd, h01[kk].y);
                FFMA2(acc[0][2], wd, h45[kk].x);
                FFMA2(acc[0][3], wd, h45[kk].y);
            }
#pragma unroll
            for (int kk = 0; kk < 4; kk++) {
                unsigned long long wd; DUP2(wd, wzreg[(j4 << 2) + kk]);
                FFMA2(acc[1][0], wd, h01[kk].x);
                FFMA2(acc[1][1], wd, h01[kk].y);
                FFMA2(acc[1][2], wd, h45[kk].x);
                FFMA2(acc[1][3], wd, h45[kk].y);
            }
            {
                float4 wv = *reinterpret_cast<const float4*>(
                    &swp[(((kq * 3 + 2) << 2) + j4) * 128 + (ud << 2)]);
                float wf[4] = {wv.x, wv.y, wv.z, wv.w};
#pragma unroll
                for (int kk = 0; kk < 4; kk++) {
                    unsigned long long wd; DUP2(wd, wf[kk]);
                    FFMA2(acc[2][0], wd, h01[kk].x);
                    FFMA2(acc[2][1], wd, h01[kk].y);
                    FFMA2(acc[2][2], wd, h45[kk].x);
                    FFMA2(acc[2][3], wd, h45[kk].y);
                }
            }
        }
#pragma unroll
        for (int g = 0; g < 3; g++)
#pragma unroll
            for (int b = 0; b < 4; b++)
                redq[redbase_st + ((g << 2) + b) * RED_GSTR] = acc[g][b];
        __syncthreads();   // rendezvous; warps 8-15 run ahead to next step's wait

        // ---- gate warps only: reduce + gates + broadcast ----
        if (tid < 256) {
            unsigned long long s[3];
#pragma unroll
            for (int g = 0; g < 3; g++) {
                const unsigned long long* rp =
                    redq + ug * RED_USTR + ((g << 2) + (bl >> 1)) * RED_GSTR;
                unsigned long long s0 = rp[0], s1 = rp[1], s2 = rp[2], s3 = rp[3];
                ADDF2(s0, s0, rp[4]);  ADDF2(s1, s1, rp[5]);
                ADDF2(s2, s2, rp[6]);  ADDF2(s3, s3, rp[7]);
                ADDF2(s0, s0, rp[8]);  ADDF2(s1, s1, rp[9]);
                ADDF2(s0, s0, rp[12]); ADDF2(s1, s1, rp[13]);
                ADDF2(s2, s2, rp[10]); ADDF2(s3, s3, rp[11]);
                ADDF2(s2, s2, rp[14]); ADDF2(s3, s3, rp[15]);
                ADDF2(s0, s0, s1); ADDF2(s2, s2, s3);
                ADDF2(s0, s0, s2);
                s[g] = s0;
            }
            float lo, hi;
            unpack2(s[0], lo, hi); float ghr = (bl & 1) ? hi : lo;
            unpack2(s[1], lo, hi); float ghz = (bl & 1) ? hi : lo;
            unpack2(s[2], lo, hi); float ghn = (bl & 1) ? hi : lo;

            float r = fast_sigmoid(ir + ghr + br);
            float z = fast_sigmoid(iz + ghz + bz);
            float n = fast_tanh(in_ + r * (ghn + bn2));
            float hnew = (1.f - z) * n + z * hold;

            stg[(ps << 8) + (ug << 3) + bl] = hnew;
            asm volatile("bar.sync 1, 256;" ::: "memory");

            // broadcast: 8 async 1KB bulk copies crediting peers' mbar[crank]
            if (tid < 8) {
                asm volatile("fence.proxy.async.shared::cta;" ::: "memory");
                uint32_t dst = p ? dstB : dstA;
                uint32_t src = stg_u32 + (uint32_t)(ps << 10);
                asm volatile(
                    "cp.async.bulk.shared::cluster.shared::cta.mbarrier::complete_tx::bytes "
                    "[%0], [%1], %2, [%3];"
                    :: "r"(dst), "r"(src), "r"(1024), "r"(rmbar) : "memory");
            }
            // gmem output overlaps the in-flight broadcast
            if (gru == 0) {
                if (t == qm1) d_out[(size_t)bgl * Hv + ugx] = hnew;
            } else {
                atomicAdd(&fout[((size_t)bgl * Sv + t) * Hv + ugx], hnew);
            }
        }
    }

    // ---- drain ----
    if (tid < 8) {
        asm volatile("cp.async.bulk.commit_group;" ::: "memory");
        asm volatile("cp.async.bulk.wait_group 0;" ::: "memory");
        mbar_wait_cluster(mbar_u32 + tid * 8, (uint32_t)((T - 1) & 1));
    }
    __syncthreads();
    asm volatile("barrier.cluster.arrive.aligned;" ::: "memory");
    asm volatile("barrier.cluster.wait.aligned;"   ::: "memory");
}

// ---------------- launch ----------------
extern "C" void kernel_launch(void* const* d_in, const int* in_sizes, int n_in,
                              void* d_out, int out_size) {
    const int*   queries = (const int*)d_in[0];
    const int*   qlen    = (const int*)d_in[1];
    const int*   docs    = (const int*)d_in[2];
    const int*   slen    = (const int*)d_in[3];
    const float* emb     = (const float*)d_in[4];
    const float* q_wih   = (const float*)d_in[5];
    const float* q_whh   = (const float*)d_in[6];
    const float* q_bih   = (const float*)d_in[7];
    const float* q_bhh   = (const float*)d_in[8];
    const float* f_wih   = (const float*)d_in[9];
    const float* f_whh   = (const float*)d_in[10];
    const float* f_bih   = (const float*)d_in[11];
    const float* f_bhh   = (const float*)d_in[12];
    const float* b_wih   = (const float*)d_in[13];
    const float* b_whh   = (const float*)d_in[14];
    const float* b_bih   = (const float*)d_in[15];
    const float* b_bhh   = (const float*)d_in[16];
    float* out = (float*)d_out;

    // bytes: swp 98304 + shT 16384 + redv 104960 + stg 4096 + mbars/pad 96
    const int GRU_SMEM = 24576 * 4 + 4096 * 4 + 2 * REDBUF * 8 + 1024 * 4 + 96;
    cudaFuncSetAttribute(gru_cluster, cudaFuncAttributeMaxDynamicSharedMemorySize, GRU_SMEM);

    facts_kernel<<<Bv * Sv, 320>>>(docs, slen, emb, out);

    dim3 gg(6, 20);
    xg_gemm<<<gg, 512>>>(queries, emb, q_wih, f_wih, b_wih, q_bih, f_bih, b_bih);

    gru_cluster<<<96, 512, GRU_SMEM>>>(qlen, q_whh, f_whh, b_whh,
                                       q_bhh, f_bhh, b_bhh, out);
}

// round 15
// speedup vs baseline: 1.0829x; 1.0431x over previous
#include <cuda_runtime.h>
#include <math.h>
#include <stdint.h>

#define Bv   32
#define QL   32
#define DOCL 2048
#define Sv   64
#define Ev   300
#define Hv   256
#define G3   768    // 3*H
#define KP   304    // padded K for GEMM
#define CLS  8      // cluster size

// ---------------- scratch ----------------
__device__ float g_facts[Bv*Sv*Ev];
__device__ float g_xg_q[Bv*QL*G3];
__device__ float g_xg_f[Bv*Sv*G3];
__device__ float g_xg_b[Bv*Sv*G3];

// packed 2xfp32 ops
#define FFMA2(acc, a, b) asm("fma.rn.f32x2 %0, %1, %2, %0;" : "+l"(acc) : "l"(a), "l"(b))
#define ADDF2(o, a, b)   asm("add.rn.f32x2 %0, %1, %2;" : "=l"(o) : "l"(a), "l"(b))
#define DUP2(d, s)       asm("mov.b64 %0, {%1, %1};" : "=l"(d) : "f"(s))

__device__ __forceinline__ void unpack2(unsigned long long v, float& lo, float& hi) {
    asm("mov.b64 {%0,%1}, %2;" : "=f"(lo), "=f"(hi) : "l"(v));
}
__device__ __forceinline__ float fast_sigmoid(float x) {
    return 1.f / (1.f + __expf(-x));
}
__device__ __forceinline__ float fast_tanh(float x) {
    return 2.f / (1.f + __expf(-2.f * x)) - 1.f;
}
__device__ __forceinline__ void mbar_wait_cluster(uint32_t mbar, uint32_t parity) {
    asm volatile(
        "{\n\t"
        ".reg .pred P;\n\t"
        "MWL_%=:\n\t"
        "mbarrier.try_wait.parity.acquire.cluster.shared::cta.b64 P, [%0], %1, 0x989680;\n\t"
        "@!P bra MWL_%=;\n\t"
        "}" :: "r"(mbar), "r"(parity) : "memory");
}

// ---------------- facts: float4 gather, 4 sentences per block ----------------
// grid 512, block 320. Thread roles:
//   tid<4:    compute start/len for sentence sid=tid
//   tid<128:  load tokens (sid = tid>>5, i = tid&31)
//   tid<300:  gather: sid = tid/75, c = tid%75 (float4 column)
//   tid<256:  zero f_out slice; tid==300 && bs0%64==0: num_facts
__global__ void facts_kernel(const int* __restrict__ docs,
                             const int* __restrict__ slen,
                             const float* __restrict__ emb,
                             float* __restrict__ d_out) {
    __shared__ int toks[4][32];
    __shared__ int sLen[4];
    __shared__ int sStart[4];
    int bs0 = blockIdx.x * 4;
    int b = bs0 >> 6;
    int tid = threadIdx.x;

    // zero this block's 4x256-float slice of f_out (for GRU atomicAdd)
    if (tid < 256) {
        reinterpret_cast<float4*>(d_out + Bv * Hv)[blockIdx.x * 256 + tid] =
            make_float4(0.f, 0.f, 0.f, 0.f);
    }
    // num_facts for batch b (one block per batch)
    if ((bs0 & 63) == 0 && tid == 300) {
        int c = 0;
        const int* sl = slen + b * Sv;
        for (int ss = 0; ss < Sv; ss++) c += (sl[ss] > 0) ? 1 : 0;
        d_out[Bv * Hv + Bv * Sv * Hv + b] = (float)c;
    }

    if (tid < 4) {
        int s = (bs0 & 63) + tid;
        const int* sl = slen + b * Sv;
        int start = 0;
        for (int i = 0; i < s; i++) start += sl[i];
        int len = sl[s];
        if (len > DOCL - start) len = DOCL - start;
        if (len > 32) len = 32;   // toks capacity (L = DOC/S = 32)
        sStart[tid] = start;
        sLen[tid] = len;
    }
    __syncthreads();
    if (tid < 128) {
        int sid = tid >> 5, i = tid & 31;
        int len = sLen[sid];
        if (i < len) toks[sid][i] = docs[b * DOCL + sStart[sid] + i];
    }
    __syncthreads();

    if (tid < 300) {
        int sid = tid / 75, c = tid - sid * 75;
        int len = sLen[sid];
        const int* tk = toks[sid];
        float4 A0 = make_float4(0.f, 0.f, 0.f, 0.f), A1 = A0, A2 = A0, A3 = A0;
        int i = 0;
        for (; i + 4 <= len; i += 4) {
            float4 v0 = *reinterpret_cast<const float4*>(emb + (size_t)tk[i]     * Ev + c * 4);
            float4 v1 = *reinterpret_cast<const float4*>(emb + (size_t)tk[i + 1] * Ev + c * 4);
            float4 v2 = *reinterpret_cast<const float4*>(emb + (size_t)tk[i + 2] * Ev + c * 4);
            float4 v3 = *reinterpret_cast<const float4*>(emb + (size_t)tk[i + 3] * Ev + c * 4);
            A0.x += v0.x; A0.y += v0.y; A0.z += v0.z; A0.w += v0.w;
            A1.x += v1.x; A1.y += v1.y; A1.z += v1.z; A1.w += v1.w;
            A2.x += v2.x; A2.y += v2.y; A2.z += v2.z; A2.w += v2.w;
            A3.x += v3.x; A3.y += v3.y; A3.z += v3.z; A3.w += v3.w;
        }
        for (; i < len; i++) {
            float4 v0 = *reinterpret_cast<const float4*>(emb + (size_t)tk[i] * Ev + c * 4);
            A0.x += v0.x; A0.y += v0.y; A0.z += v0.z; A0.w += v0.w;
        }
        float d = (len > 0) ? (float)len : 1.0f;
        float inv = 1.0f / d;
        float4 r;
        r.x = ((A0.x + A1.x) + (A2.x + A3.x)) * inv;
        r.y = ((A0.y + A1.y) + (A2.y + A3.y)) * inv;
        r.z = ((A0.z + A1.z) + (A2.z + A3.z)) * inv;
        r.w = ((A0.w + A1.w) + (A2.w + A3.w)) * inv;
        *reinterpret_cast<float4*>(g_facts + (size_t)(bs0 + sid) * Ev + c * 4) = r;
    }
}

// ---------------- merged xg GEMM: 5120 x 768 x 304 (unchanged from 235.5) ----------
__global__ __launch_bounds__(512, 1) void xg_gemm(
        const int* __restrict__ queries, const float* __restrict__ emb,
        const float* __restrict__ qwih, const float* __restrict__ fwih,
        const float* __restrict__ bwih,
        const float* __restrict__ qbih, const float* __restrict__ fbih,
        const float* __restrict__ bbih) {
    __shared__ float As[2][16][264];
    __shared__ float Bs[2][16][132];

    int m0 = blockIdx.y * 256, n0 = blockIdx.x * 128;
    int which = (m0 < 1024) ? 0 : ((m0 < 3072) ? 1 : 2);
    int mbase = (which == 0) ? 0 : (which == 1) ? 1024 : 3072;
    const float* wih = (which == 0) ? qwih : (which == 1) ? fwih : bwih;
    const float* bih = (which == 0) ? qbih : (which == 1) ? fbih : bbih;
    float* outb = ((which == 0) ? g_xg_q : (which == 1) ? g_xg_f : g_xg_b)
                  + (size_t)(m0 - mbase) * G3;

    int tid = threadIdx.x, tx = tid & 15, ty = tid >> 4;

    const float* asrc[2];
    int ac[2];
#pragma unroll
    for (int i = 0; i < 2; i++) {
        int idx = tid + i * 512;
        int r = idx >> 2;
        ac[i] = idx & 3;
        int m = m0 + r;
        asrc[i] = (which == 0) ? (emb + (size_t)queries[m] * Ev)
                               : (g_facts + (size_t)(m - mbase) * Ev);
    }
    int ar0 = (tid) >> 2, ar1 = (tid + 512) >> 2;
    int bn = tid >> 2, bkq = tid & 3;
    const float* brow = wih + (size_t)(n0 + bn) * Ev;

    unsigned long long acc[8][4];
#pragma unroll
    for (int i = 0; i < 8; i++)
#pragma unroll
        for (int j = 0; j < 4; j++) acc[i][j] = 0ull;

    float4 avp0, avp1, bvp;
#define LOAD_REGS(K0) do {                                                    \
        int k0_ = (K0);                                                       \
        int ka0 = k0_ + ac[0] * 4, ka1 = k0_ + ac[1] * 4, kb = k0_ + bkq * 4; \
        avp0 = (ka0 < Ev) ? *reinterpret_cast<const float4*>(asrc[0] + ka0)   \
                          : make_float4(0.f, 0.f, 0.f, 0.f);                  \
        avp1 = (ka1 < Ev) ? *reinterpret_cast<const float4*>(asrc[1] + ka1)   \
                          : make_float4(0.f, 0.f, 0.f, 0.f);                  \
        bvp  = (kb  < Ev) ? *reinterpret_cast<const float4*>(brow + kb)       \
                          : make_float4(0.f, 0.f, 0.f, 0.f);                  \
    } while (0)

    LOAD_REGS(0);

    for (int kt = 0; kt < KP / 16; kt++) {
        int buf = kt & 1;
        As[buf][ac[0]*4+0][ar0] = avp0.x; As[buf][ac[0]*4+1][ar0] = avp0.y;
        As[buf][ac[0]*4+2][ar0] = avp0.z; As[buf][ac[0]*4+3][ar0] = avp0.w;
        As[buf][ac[1]*4+0][ar1] = avp1.x; As[buf][ac[1]*4+1][ar1] = avp1.y;
        As[buf][ac[1]*4+2][ar1] = avp1.z; As[buf][ac[1]*4+3][ar1] = avp1.w;
        Bs[buf][bkq*4+0][bn] = bvp.x; Bs[buf][bkq*4+1][bn] = bvp.y;
        Bs[buf][bkq*4+2][bn] = bvp.z; Bs[buf][bkq*4+3][bn] = bvp.w;
        __syncthreads();

        if (kt + 1 < KP / 16) LOAD_REGS((kt + 1) * 16);

#pragma unroll
        for (int k = 0; k < 16; k++) {
            float4 a0 = *reinterpret_cast<const float4*>(&As[buf][k][ty * 8]);
            float4 a1 = *reinterpret_cast<const float4*>(&As[buf][k][ty * 8 + 4]);
            ulonglong2 b01 = *reinterpret_cast<const ulonglong2*>(&Bs[buf][k][tx * 8]);
            ulonglong2 b23 = *reinterpret_cast<const ulonglong2*>(&Bs[buf][k][tx * 8 + 4]);
            float af[8] = {a0.x, a0.y, a0.z, a0.w, a1.x, a1.y, a1.z, a1.w};
#pragma unroll
            for (int i = 0; i < 8; i++) {
                unsigned long long ad; DUP2(ad, af[i]);
                FFMA2(acc[i][0], ad, b01.x);
                FFMA2(acc[i][1], ad, b01.y);
                FFMA2(acc[i][2], ad, b23.x);
                FFMA2(acc[i][3], ad, b23.y);
            }
        }
    }
#undef LOAD_REGS
#pragma unroll
    for (int i = 0; i < 8; i++) {
        float* orow = outb + (size_t)(ty * 8 + i) * G3 + n0 + tx * 8;
#pragma unroll
        for (int jp = 0; jp < 4; jp++) {
            float lo, hi; unpack2(acc[i][jp], lo, hi);
            orow[2*jp]   = lo + bih[n0 + tx*8 + 2*jp];
            orow[2*jp+1] = hi + bih[n0 + tx*8 + 2*jp + 1];
        }
    }
}

// ---------------- GRU: per-slice mbarriers, wait-then-arm (unchanged from 235.5) ----
#define RED_USTR 205
#define RED_GSTR 17
#define REDBUF  (32 * RED_USTR)   // u64 per parity buffer
extern "C" __global__ void __cluster_dims__(CLS, 1, 1) __launch_bounds__(512, 1)
gru_cluster(const int* __restrict__ qlen,
            const float* __restrict__ qwhh, const float* __restrict__ fwhh,
            const float* __restrict__ bwhh,
            const float* __restrict__ qbhh, const float* __restrict__ fbhh,
            const float* __restrict__ bbhh,
            float* __restrict__ d_out) {
    extern __shared__ float sm[];
    float* swp = sm;                                         // 24576 floats
    float* shT = sm + 24576;                                 // 4096 floats [2][256][8]
    unsigned long long* redv = (unsigned long long*)(sm + 24576 + 4096);  // 2 x REDBUF
    float* stg = (float*)(redv + 2 * REDBUF);                // [4][256]
    unsigned long long* mbar = (unsigned long long*)(stg + 1024);  // [8]

    int cid = blockIdx.x / CLS;
    int crank = blockIdx.x - cid * CLS;
    int gru = cid >> 2, bg = cid & 3;
    int tid = threadIdx.x;

    const float* whh = (gru == 0) ? qwhh : (gru == 1) ? fwhh : bwhh;
    const float* bhh = (gru == 0) ? qbhh : (gru == 1) ? fbhh : bbhh;
    const float* xg  = (gru == 0) ? g_xg_q : (gru == 1) ? g_xg_f : g_xg_b;
    float* fout = d_out + Bv * Hv;
    int T = (gru == 0) ? QL : Sv;

    uint32_t shT_u32, mbar_u32, stg_u32;
    asm("{ .reg .u64 t; cvta.to.shared.u64 t, %1; cvt.u32.u64 %0, t; }"
        : "=r"(shT_u32) : "l"(shT));
    asm("{ .reg .u64 t; cvta.to.shared.u64 t, %1; cvt.u32.u64 %0, t; }"
        : "=r"(mbar_u32) : "l"(mbar));
    asm("{ .reg .u64 t; cvta.to.shared.u64 t, %1; cvt.u32.u64 %0, t; }"
        : "=r"(stg_u32) : "l"(stg));

    // ---- init: repack weights; zero h + stg; init 8 mbarriers; arm phase 0 ----
    for (int i = tid; i < 96 * 64; i += 512) {
        int gi = i >> 6, k4 = i & 63;
        int g = gi >> 5, u = gi & 31;
        float4 v = *reinterpret_cast<const float4*>(
            &whh[(size_t)((g << 8) + (crank << 5) + u) * Hv + (k4 << 2)]);
        int kq = k4 >> 2, j4 = k4 & 3;
        *reinterpret_cast<float4*>(&swp[(((kq * 3 + g) << 2) + j4) * 128 + (u << 2)]) = v;
    }
    for (int i = tid; i < 4096; i += 512) shT[i] = 0.f;
    for (int i = tid; i < 1024; i += 512) stg[i] = 0.f;
    if (tid < 8) {
        asm volatile("mbarrier.init.shared.b64 [%0], %1;"
                     :: "r"(mbar_u32 + tid * 8), "r"(1) : "memory");
        asm volatile("mbarrier.arrive.expect_tx.shared.b64 _, [%0], %1;"
                     :: "r"(mbar_u32 + tid * 8), "r"(1024) : "memory");
    }
    __syncthreads();
    asm volatile("barrier.cluster.arrive.aligned;" ::: "memory");
    asm volatile("barrier.cluster.wait.aligned;"   ::: "memory");

    // ---- dot role: r and z gate weights in registers ----
    int ud = tid & 31, kq = tid >> 5;
    float wrreg[16], wzreg[16];
#pragma unroll
    for (int j4 = 0; j4 < 4; j4++) {
        float4 wv = *reinterpret_cast<const float4*>(
            &swp[(((kq * 3 + 0) << 2) + j4) * 128 + (ud << 2)]);
        wrreg[(j4 << 2) + 0] = wv.x; wrreg[(j4 << 2) + 1] = wv.y;
        wrreg[(j4 << 2) + 2] = wv.z; wrreg[(j4 << 2) + 3] = wv.w;
        float4 zv = *reinterpret_cast<const float4*>(
            &swp[(((kq * 3 + 1) << 2) + j4) * 128 + (ud << 2)]);
        wzreg[(j4 << 2) + 0] = zv.x; wzreg[(j4 << 2) + 1] = zv.y;
        wzreg[(j4 << 2) + 2] = zv.z; wzreg[(j4 << 2) + 3] = zv.w;
    }
    uint32_t mywait = mbar_u32 + (uint32_t)((kq >> 1) << 3);
    bool armer = ((tid & 63) == 0);

    // ---- gate role: tid<256, 1 batch each ----
    int ug = tid >> 3, bl = tid & 7;
    int ugx = (crank << 5) + ug;
    int bgl = (bg << 3) + bl;
    float br = 0.f, bz = 0.f, bn2 = 0.f;
    int qm1 = -2;
    const float* xgb = nullptr;
    if (tid < 256) {
        br = bhh[ugx]; bz = bhh[256 + ugx]; bn2 = bhh[512 + ugx];
        if (gru == 0) qm1 = qlen[bgl] - 1;
        xgb = xg + (size_t)bgl * T * G3;
    }

    // bulk-copy role (tid<8)
    uint32_t dstA = 0, dstB = 0, rmbar = 0;
    if (tid < 8) {
        uint32_t l0 = shT_u32 + 8192u + (uint32_t)(crank << 10);  // p=0 -> buf1
        uint32_t l1 = shT_u32 + (uint32_t)(crank << 10);          // p=1 -> buf0
        uint32_t lm = mbar_u32 + (uint32_t)(crank << 3);
        asm("mapa.shared::cluster.u32 %0, %1, %2;" : "=r"(dstA)  : "r"(l0), "r"(tid));
        asm("mapa.shared::cluster.u32 %0, %1, %2;" : "=r"(dstB)  : "r"(l1), "r"(tid));
        asm("mapa.shared::cluster.u32 %0, %1, %2;" : "=r"(rmbar) : "r"(lm), "r"(tid));
    }

    int redbase_st = ud * RED_USTR + kq;

    for (int step = 0; step < T; step++) {
        int t = (gru == 2) ? (T - 1 - step) : step;
        int p = step & 1;
        int ps = step & 3;
        int pprev = (step - 1) & 3;
        unsigned long long* redq = redv + (size_t)(step & 1) * REDBUF;

        // gate-role x prefetch (independent of h slices)
        float ir = 0.f, iz = 0.f, in_ = 0.f, hold = 0.f;
        if (tid < 256) {
            const float* xr = xgb + (size_t)t * G3;
            ir = xr[ugx]; iz = xr[256 + ugx]; in_ = xr[512 + ugx];
            hold = stg[(pprev << 8) + (ug << 3) + bl];
        }

        // per-warp wait for the one needed slice, then re-arm that barrier
        if (step > 0) {
            mbar_wait_cluster(mywait, (uint32_t)((step - 1) & 1));
            if (armer) {
                asm volatile("mbarrier.arrive.expect_tx.shared.b64 _, [%0], %1;"
                             :: "r"(mywait), "r"(1024) : "memory");
            }
        }

        // ---- dot: 3 gates x 16 k x 8 batches per thread ----
        unsigned long long acc[3][4];
#pragma unroll
        for (int g = 0; g < 3; g++)
#pragma unroll
            for (int b = 0; b < 4; b++) acc[g][b] = 0ull;

        const float* hT = shT + ((p << 8) + (kq << 4)) * 8;
#pragma unroll
        for (int j4 = 0; j4 < 4; j4++) {
            ulonglong2 h01[4], h45[4];
#pragma unroll
            for (int kk = 0; kk < 4; kk++) {
                const ulonglong2* hr = reinterpret_cast<const ulonglong2*>(
                    hT + ((j4 << 2) + kk) * 8);
                h01[kk] = hr[0];
                h45[kk] = hr[1];
            }
#pragma unroll
            for (int kk = 0; kk < 4; kk++) {
                unsigned long long wd; DUP2(wd, wrreg[(j4 << 2) + kk]);
                FFMA2(acc[0][0], wd, h01[kk].x);
                FFMA2(acc[0][1], wd, h01[kk].y);
                FFMA2(acc[0][2], wd, h45[kk].x);
                FFMA2(acc[0][3], wd, h45[kk].y);
            }
#pragma unroll
            for (int kk = 0; kk < 4; kk++) {
                unsigned long long wd; DUP2(wd, wzreg[(j4 << 2) + kk]);
                FFMA2(acc[1][0], wd, h01[kk].x);
                FFMA2(acc[1][1], wd, h01[kk].y);
                FFMA2(acc[1][2], wd, h45[kk].x);
                FFMA2(acc[1][3], wd, h45[kk].y);
            }
            {
                float4 wv = *reinterpret_cast<const float4*>(
                    &swp[(((kq * 3 + 2) << 2) + j4) * 128 + (ud << 2)]);
                float wf[4] = {wv.x, wv.y, wv.z, wv.w};
#pragma unroll
                for (int kk = 0; kk < 4; kk++) {
                    unsigned long long wd; DUP2(wd, wf[kk]);
                    FFMA2(acc[2][0], wd, h01[kk].x);
                    FFMA2(acc[2][1], wd, h01[kk].y);
                    FFMA2(acc[2][2], wd, h45[kk].x);
                    FFMA2(acc[2][3], wd, h45[kk].y);
                }
            }
        }
#pragma unroll
        for (int g = 0; g < 3; g++)
#pragma unroll
            for (int b = 0; b < 4; b++)
                redq[redbase_st + ((g << 2) + b) * RED_GSTR] = acc[g][b];
        __syncthreads();   // rendezvous; warps 8-15 run ahead to next step's wait

        // ---- gate warps only: reduce + gates + broadcast ----
        if (tid < 256) {
            unsigned long long s[3];
#pragma unroll
            for (int g = 0; g < 3; g++) {
                const unsigned long long* rp =
                    redq + ug * RED_USTR + ((g << 2) + (bl >> 1)) * RED_GSTR;
                unsigned long long s0 = rp[0], s1 = rp[1], s2 = rp[2], s3 = rp[3];
                ADDF2(s0, s0, rp[4]);  ADDF2(s1, s1, rp[5]);
                ADDF2(s2, s2, rp[6]);  ADDF2(s3, s3, rp[7]);
                ADDF2(s0, s0, rp[8]);  ADDF2(s1, s1, rp[9]);
                ADDF2(s0, s0, rp[12]); ADDF2(s1, s1, rp[13]);
                ADDF2(s2, s2, rp[10]); ADDF2(s3, s3, rp[11]);
                ADDF2(s2, s2, rp[14]); ADDF2(s3, s3, rp[15]);
                ADDF2(s0, s0, s1); ADDF2(s2, s2, s3);
                ADDF2(s0, s0, s2);
                s[g] = s0;
            }
            float lo, hi;
            unpack2(s[0], lo, hi); float ghr = (bl & 1) ? hi : lo;
            unpack2(s[1], lo, hi); float ghz = (bl & 1) ? hi : lo;
            unpack2(s[2], lo, hi); float ghn = (bl & 1) ? hi : lo;

            float r = fast_sigmoid(ir + ghr + br);
            float z = fast_sigmoid(iz + ghz + bz);
            float n = fast_tanh(in_ + r * (ghn + bn2));
            float hnew = (1.f - z) * n + z * hold;

            stg[(ps << 8) + (ug << 3) + bl] = hnew;
            asm volatile("bar.sync 1, 256;" ::: "memory");

            // broadcast: 8 async 1KB bulk copies crediting peers' mbar[crank]
            if (tid < 8) {
                asm volatile("fence.proxy.async.shared::cta;" ::: "memory");
                uint32_t dst = p ? dstB : dstA;
                uint32_t src = stg_u32 + (uint32_t)(ps << 10);
                asm volatile(
                    "cp.async.bulk.shared::cluster.shared::cta.mbarrier::complete_tx::bytes "
                    "[%0], [%1], %2, [%3];"
                    :: "r"(dst), "r"(src), "r"(1024), "r"(rmbar) : "memory");
            }
            // gmem output overlaps the in-flight broadcast
            if (gru == 0) {
                if (t == qm1) d_out[(size_t)bgl * Hv + ugx] = hnew;
            } else {
                atomicAdd(&fout[((size_t)bgl * Sv + t) * Hv + ugx], hnew);
            }
        }
    }

    // ---- drain ----
    if (tid < 8) {
        asm volatile("cp.async.bulk.commit_group;" ::: "memory");
        asm volatile("cp.async.bulk.wait_group 0;" ::: "memory");
        mbar_wait_cluster(mbar_u32 + tid * 8, (uint32_t)((T - 1) & 1));
    }
    __syncthreads();
    asm volatile("barrier.cluster.arrive.aligned;" ::: "memory");
    asm volatile("barrier.cluster.wait.aligned;"   ::: "memory");
}

// ---------------- launch ----------------
extern "C" void kernel_launch(void* const* d_in, const int* in_sizes, int n_in,
                              void* d_out, int out_size) {
    const int*   queries = (const int*)d_in[0];
    const int*   qlen    = (const int*)d_in[1];
    const int*   docs    = (const int*)d_in[2];
    const int*   slen    = (const int*)d_in[3];
    const float* emb     = (const float*)d_in[4];
    const float* q_wih   = (const float*)d_in[5];
    const float* q_whh   = (const float*)d_in[6];
    const float* q_bih   = (const float*)d_in[7];
    const float* q_bhh   = (const float*)d_in[8];
    const float* f_wih   = (const float*)d_in[9];
    const float* f_whh   = (const float*)d_in[10];
    const float* f_bih   = (const float*)d_in[11];
    const float* f_bhh   = (const float*)d_in[12];
    const float* b_wih   = (const float*)d_in[13];
    const float* b_whh   = (const float*)d_in[14];
    const float* b_bih   = (const float*)d_in[15];
    const float* b_bhh   = (const float*)d_in[16];
    float* out = (float*)d_out;

    // bytes: swp 98304 + shT 16384 + redv 104960 + stg 4096 + mbars/pad 96
    const int GRU_SMEM = 24576 * 4 + 4096 * 4 + 2 * REDBUF * 8 + 1024 * 4 + 96;
    cudaFuncSetAttribute(gru_cluster, cudaFuncAttributeMaxDynamicSharedMemorySize, GRU_SMEM);

    facts_kernel<<<Bv * Sv / 4, 320>>>(docs, slen, emb, out);

    dim3 gg(6, 20);
    xg_gemm<<<gg, 512>>>(queries, emb, q_wih, f_wih, b_wih, q_bih, f_bih, b_bih);

    gru_cluster<<<96, 512, GRU_SMEM>>>(qlen, q_whh, f_whh, b_whh,
                                       q_bhh, f_bhh, b_bhh, out);
}